// round 8
// baseline (speedup 1.0000x reference)
#include <cuda_runtime.h>
#include <math.h>
#include <stdint.h>

#define NN    50000
#define FH    128      // H*C
#define NH    4
#define EMAX  800000
#define NEG   0.2f
#define NBMAX 256
#define NTB   296                          // persistent grid (all co-resident)
#define PSTR  (NTB * 256)                  // 75776
#define EPT   12                           // ceil((EMAX+NN)/PSTR)

// ---------------- scratch (static device globals; no runtime alloc) --------
__device__ float  g_xp[NN * FH];           // projected features fp32 [N][128]
__device__ float  g_asrc[NN * NH];
__device__ float  g_adst[NN * NH];
__device__ int    g_deg[NN];               // re-zeroed inside scan phase
__device__ int    g_rowptr[NN + 1];
__device__ int    g_bval[NBMAX];
__device__ volatile int g_bflag[NBMAX];
__device__ int    g_sync1, g_sync2;        // reset by k_agg (runs after)
__device__ int    g_csr[EMAX + NN];

// ---------------- helpers ---------------------------------------------------
__device__ __forceinline__ void f2tf32x2(float f, uint32_t& hi, uint32_t& lo) {
    asm("cvt.rna.tf32.f32 %0, %1;" : "=r"(hi) : "f"(f));
    float d = f - __uint_as_float(hi);
    asm("cvt.rna.tf32.f32 %0, %1;" : "=r"(lo) : "f"(d));
}

__device__ __forceinline__ void mma_tf32(float* c, const uint32_t* a, const uint32_t* b) {
    asm volatile(
        "mma.sync.aligned.m16n8k8.row.col.f32.tf32.tf32.f32 "
        "{%0,%1,%2,%3}, {%4,%5,%6,%7}, {%8,%9}, {%0,%1,%2,%3};"
        : "+f"(c[0]), "+f"(c[1]), "+f"(c[2]), "+f"(c[3])
        : "r"(a[0]), "r"(a[1]), "r"(a[2]), "r"(a[3]), "r"(b[0]), "r"(b[1]));
}

__device__ __forceinline__ void ffma2(unsigned long long& acc, unsigned long long v,
                                      unsigned long long w2) {
    asm("fma.rn.f32x2 %0, %1, %2, %0;" : "+l"(acc) : "l"(v), "l"(w2));
}

// grid-wide barrier: only thread 0 of each block polls (all blocks resident)
__device__ __forceinline__ void gsync(int* ctr, int target) {
    __syncthreads();
    __threadfence();
    if (threadIdx.x == 0) {
        atomicAdd(ctr, 1);
        while (*(volatile int*)ctr < target) { }
        __threadfence();
    }
    __syncthreads();
}

// ---------------- GEMM: xp = x @ W^T via 3xTF32 tensor cores ----------------
#define XP 20
#define WP 136
__global__ __launch_bounds__(256) void k_gemm(
    const float* __restrict__ x, const float* __restrict__ W,
    const float* __restrict__ attS, const float* __restrict__ attD, int n)
{
    __shared__ float xsh[128 * XP], xsl[128 * XP];
    __shared__ float wth[16 * WP],  wtl[16 * WP];
    __shared__ float sAttS[128], sAttD[128];
    __shared__ float sAs[128 * 4], sAd[128 * 4];

    int t = threadIdx.x;
    if (t < 128) { sAttS[t] = attS[t]; sAttD[t] = attD[t]; }

    int row0 = blockIdx.x * 128;
    int wid = t >> 5, lane = t & 31;
    int wm = wid >> 1, wn = wid & 1;
    int g = lane >> 2, q4 = lane & 3;

    float acc[2][8][4];
#pragma unroll
    for (int mt = 0; mt < 2; mt++)
#pragma unroll
        for (int nt = 0; nt < 8; nt++)
#pragma unroll
            for (int c = 0; c < 4; c++) acc[mt][nt][c] = 0.f;

    for (int kc = 0; kc < 128; kc += 16) {
#pragma unroll
        for (int j = 0; j < 2; j++) {
            int idx = t + 256 * j;
            int r = idx >> 2, q = idx & 3;
            float4 v = make_float4(0.f, 0.f, 0.f, 0.f);
            if (row0 + r < n) v = *(const float4*)(x + (size_t)(row0 + r) * 128 + kc + q * 4);
            uint32_t h0, l0, h1, l1, h2, l2, h3, l3;
            f2tf32x2(v.x, h0, l0); f2tf32x2(v.y, h1, l1);
            f2tf32x2(v.z, h2, l2); f2tf32x2(v.w, h3, l3);
            float* ph = xsh + r * XP + q * 4;
            float* pl = xsl + r * XP + q * 4;
            ph[0] = __uint_as_float(h0); ph[1] = __uint_as_float(h1);
            ph[2] = __uint_as_float(h2); ph[3] = __uint_as_float(h3);
            pl[0] = __uint_as_float(l0); pl[1] = __uint_as_float(l1);
            pl[2] = __uint_as_float(l2); pl[3] = __uint_as_float(l3);
        }
#pragma unroll
        for (int j = 0; j < 2; j++) {
            int idx = t + 256 * j;
            int oc = idx >> 2, q = idx & 3;
            float4 v = *(const float4*)(W + (size_t)oc * 128 + kc + q * 4);
            uint32_t h0, l0, h1, l1, h2, l2, h3, l3;
            f2tf32x2(v.x, h0, l0); f2tf32x2(v.y, h1, l1);
            f2tf32x2(v.z, h2, l2); f2tf32x2(v.w, h3, l3);
            wth[(q * 4 + 0) * WP + oc] = __uint_as_float(h0);
            wth[(q * 4 + 1) * WP + oc] = __uint_as_float(h1);
            wth[(q * 4 + 2) * WP + oc] = __uint_as_float(h2);
            wth[(q * 4 + 3) * WP + oc] = __uint_as_float(h3);
            wtl[(q * 4 + 0) * WP + oc] = __uint_as_float(l0);
            wtl[(q * 4 + 1) * WP + oc] = __uint_as_float(l1);
            wtl[(q * 4 + 2) * WP + oc] = __uint_as_float(l2);
            wtl[(q * 4 + 3) * WP + oc] = __uint_as_float(l3);
        }
        __syncthreads();

#pragma unroll
        for (int kk = 0; kk < 16; kk += 8) {
            uint32_t ah[2][4], al[2][4];
#pragma unroll
            for (int mt = 0; mt < 2; mt++) {
                int r = wm * 32 + mt * 16 + g;
                int b0 = r * XP + kk + q4;
                ah[mt][0] = __float_as_uint(xsh[b0]);
                ah[mt][1] = __float_as_uint(xsh[b0 + 8 * XP]);
                ah[mt][2] = __float_as_uint(xsh[b0 + 4]);
                ah[mt][3] = __float_as_uint(xsh[b0 + 8 * XP + 4]);
                al[mt][0] = __float_as_uint(xsl[b0]);
                al[mt][1] = __float_as_uint(xsl[b0 + 8 * XP]);
                al[mt][2] = __float_as_uint(xsl[b0 + 4]);
                al[mt][3] = __float_as_uint(xsl[b0 + 8 * XP + 4]);
            }
#pragma unroll
            for (int nt = 0; nt < 8; nt++) {
                int col = wn * 64 + nt * 8 + g;
                int kb = (kk + q4) * WP + col;
                uint32_t bh[2], bl[2];
                bh[0] = __float_as_uint(wth[kb]);
                bh[1] = __float_as_uint(wth[kb + 4 * WP]);
                bl[0] = __float_as_uint(wtl[kb]);
                bl[1] = __float_as_uint(wtl[kb + 4 * WP]);
#pragma unroll
                for (int mt = 0; mt < 2; mt++) {
                    mma_tf32(acc[mt][nt], ah[mt], bh);
                    mma_tf32(acc[mt][nt], ah[mt], bl);
                    mma_tf32(acc[mt][nt], al[mt], bh);
                }
            }
        }
        __syncthreads();
    }

#pragma unroll
    for (int mt = 0; mt < 2; mt++) {
#pragma unroll
        for (int half = 0; half < 2; half++) {
            int rl = wm * 32 + mt * 16 + half * 8 + g;
            int r = row0 + rl;
            float ps0 = 0.f, pd0 = 0.f, ps1 = 0.f, pd1 = 0.f;
#pragma unroll
            for (int nt = 0; nt < 8; nt++) {
                int cbase = wn * 64 + nt * 8 + q4 * 2;
                float v0 = acc[mt][nt][half * 2 + 0];
                float v1 = acc[mt][nt][half * 2 + 1];
                float as0 = sAttS[cbase], as1 = sAttS[cbase + 1];
                float ad0 = sAttD[cbase], ad1 = sAttD[cbase + 1];
                if (nt < 4) { ps0 += v0 * as0 + v1 * as1; pd0 += v0 * ad0 + v1 * ad1; }
                else        { ps1 += v0 * as0 + v1 * as1; pd1 += v0 * ad0 + v1 * ad1; }
                if (r < n)
                    *(float2*)(g_xp + (size_t)r * 128 + cbase) = make_float2(v0, v1);
            }
            ps0 += __shfl_xor_sync(0xffffffffu, ps0, 1); ps0 += __shfl_xor_sync(0xffffffffu, ps0, 2);
            ps1 += __shfl_xor_sync(0xffffffffu, ps1, 1); ps1 += __shfl_xor_sync(0xffffffffu, ps1, 2);
            pd0 += __shfl_xor_sync(0xffffffffu, pd0, 1); pd0 += __shfl_xor_sync(0xffffffffu, pd0, 2);
            pd1 += __shfl_xor_sync(0xffffffffu, pd1, 1); pd1 += __shfl_xor_sync(0xffffffffu, pd1, 2);
            if (q4 == 0) {
                sAs[rl * 4 + wn * 2 + 0] = ps0;
                sAs[rl * 4 + wn * 2 + 1] = ps1;
                sAd[rl * 4 + wn * 2 + 0] = pd0;
                sAd[rl * 4 + wn * 2 + 1] = pd1;
            }
        }
    }
    __syncthreads();
    if (t < 128 && row0 + t < n) {
        *(float4*)(g_asrc + (size_t)(row0 + t) * 4) = *(const float4*)(sAs + t * 4);
        *(float4*)(g_adst + (size_t)(row0 + t) * 4) = *(const float4*)(sAd + t * 4);
    }
}

// ---------------- persistent CSR build: hist + scan + scatter ---------------
__global__ __launch_bounds__(256, 4) void k_csrbuild(
    const int* __restrict__ src, const int* __restrict__ dst, int n, int E)
{
    __shared__ int s[256];
    int t = threadIdx.x, b = blockIdx.x;
    int gid = b * 256 + t;

    // reset lookback flags before first sync
    if (b == 0) g_bflag[t] = 0;

    // ---- phase A: histogram; cache (dst, ordinal) in registers ----
    int dc[EPT], oc[EPT];
#pragma unroll
    for (int k = 0; k < EPT; k++) {
        int e = gid + k * PSTR;
        if (e < E) {
            int d = __ldcs(dst + e);
            dc[k] = d;
            oc[k] = atomicAdd(&g_deg[d], 1);
        }
    }
    gsync(&g_sync1, NTB);

    // ---- phase B: lookback scan of (deg+1) -> rowptr; re-zero deg ----
    int nscan = (n + 255) >> 8;
    if (b < nscan) {
        int i = gid;
        int v = 0;
        if (i < n) { v = g_deg[i] + 1; g_deg[i] = 0; }
        s[t] = v;
        __syncthreads();
#pragma unroll
        for (int off = 1; off < 256; off <<= 1) {
            int u = (t >= off) ? s[t - off] : 0;
            __syncthreads();
            s[t] += u;
            __syncthreads();
        }
        int incl = s[t];
        int agg  = s[255];
        if (t == 255) {
            g_bval[b] = agg;
            __threadfence();
            g_bflag[b] = 1;
        }
        int part = 0;
        for (int j = t; j < b; j += 256) {
            while (g_bflag[j] == 0) { }
            part += *(volatile int*)&g_bval[j];
        }
        __syncthreads();
        s[t] = part;
        __syncthreads();
#pragma unroll
        for (int off = 128; off > 0; off >>= 1) {
            if (t < off) s[t] += s[t + off];
            __syncthreads();
        }
        int excl0 = s[0];
        if (i < n) g_rowptr[i] = excl0 + incl - v;
        if (b == nscan - 1 && t == 255) g_rowptr[n] = excl0 + agg;
    }
    gsync(&g_sync2, NTB);

    // ---- phase C: atomic-free scatter from registers ----
#pragma unroll
    for (int k = 0; k < EPT; k++) {
        int e = gid + k * PSTR;
        if (e < E) {
            g_csr[g_rowptr[dc[k]] + oc[k]] = __ldcs(src + e);
        } else if (e < E + n) {
            int i = e - E;
            g_csr[g_rowptr[i + 1] - 1] = i;      // self loop in last slot
        }
    }
}

// ---------------- aggregation: one warp per destination node ----------------
__global__ __launch_bounds__(256) void k_agg(
    const float* __restrict__ bias, float* __restrict__ out, int n)
{
    // reset persistent-kernel sync counters for the next graph replay
    // (safe: k_csrbuild of this call has fully completed — stream order)
    if (blockIdx.x == 0 && threadIdx.x == 0) { g_sync1 = 0; g_sync2 = 0; }

    int warp = (blockIdx.x * blockDim.x + threadIdx.x) >> 5;
    int lane = threadIdx.x & 31;
    if (warp >= n) return;
    int nd = warp;
    int h = lane >> 3;

    int begin = g_rowptr[nd], end = g_rowptr[nd + 1];
    float adh = g_adst[nd * 4 + h];

    unsigned long long acc01 = 0ull, acc23 = 0ull;   // packed f32x2 accumulators
    float den = 0.f;
    const float* xpb = g_xp + lane * 4;

    int i = begin;
    for (; i + 4 <= end; i += 4) {
        int s0 = g_csr[i], s1 = g_csr[i + 1], s2 = g_csr[i + 2], s3 = g_csr[i + 3];
        float a0 = g_asrc[s0 * 4 + h] + adh;
        float a1 = g_asrc[s1 * 4 + h] + adh;
        float a2 = g_asrc[s2 * 4 + h] + adh;
        float a3 = g_asrc[s3 * 4 + h] + adh;
        ulonglong2 u0 = *(const ulonglong2*)(xpb + (size_t)s0 * 128);
        ulonglong2 u1 = *(const ulonglong2*)(xpb + (size_t)s1 * 128);
        ulonglong2 u2 = *(const ulonglong2*)(xpb + (size_t)s2 * 128);
        ulonglong2 u3 = *(const ulonglong2*)(xpb + (size_t)s3 * 128);
        a0 = fmaxf(a0, NEG * a0);
        a1 = fmaxf(a1, NEG * a1);
        a2 = fmaxf(a2, NEG * a2);
        a3 = fmaxf(a3, NEG * a3);
        float w0 = __expf(a0), w1 = __expf(a1), w2 = __expf(a2), w3 = __expf(a3);
        unsigned long long ww;
        asm("mov.b64 %0, {%1, %1};" : "=l"(ww) : "f"(w0));
        ffma2(acc01, u0.x, ww); ffma2(acc23, u0.y, ww);
        asm("mov.b64 %0, {%1, %1};" : "=l"(ww) : "f"(w1));
        ffma2(acc01, u1.x, ww); ffma2(acc23, u1.y, ww);
        asm("mov.b64 %0, {%1, %1};" : "=l"(ww) : "f"(w2));
        ffma2(acc01, u2.x, ww); ffma2(acc23, u2.y, ww);
        asm("mov.b64 %0, {%1, %1};" : "=l"(ww) : "f"(w3));
        ffma2(acc01, u3.x, ww); ffma2(acc23, u3.y, ww);
        den += (w0 + w1) + (w2 + w3);
    }
    for (; i < end; i++) {
        int s0 = g_csr[i];
        float a0 = g_asrc[s0 * 4 + h] + adh;
        ulonglong2 u0 = *(const ulonglong2*)(xpb + (size_t)s0 * 128);
        a0 = fmaxf(a0, NEG * a0);
        float w0 = __expf(a0);
        unsigned long long ww;
        asm("mov.b64 %0, {%1, %1};" : "=l"(ww) : "f"(w0));
        ffma2(acc01, u0.x, ww); ffma2(acc23, u0.y, ww);
        den += w0;
    }

    float ax, ay, az, aw;
    asm("mov.b64 {%0, %1}, %2;" : "=f"(ax), "=f"(ay) : "l"(acc01));
    asm("mov.b64 {%0, %1}, %2;" : "=f"(az), "=f"(aw) : "l"(acc23));

    float inv = 1.0f / (den + 1e-16f);
    float4 bb = ((const float4*)bias)[lane];
    float4 o;
    o.x = ax * inv + bb.x;
    o.y = ay * inv + bb.y;
    o.z = az * inv + bb.z;
    o.w = aw * inv + bb.w;
    o.x = o.x > 0.f ? o.x : expm1f(o.x);
    o.y = o.y > 0.f ? o.y : expm1f(o.y);
    o.z = o.z > 0.f ? o.z : expm1f(o.z);
    o.w = o.w > 0.f ? o.w : expm1f(o.w);
    ((float4*)out)[(size_t)nd * 32 + lane] = o;
}

// ---------------- launch ----------------------------------------------------
extern "C" void kernel_launch(void* const* d_in, const int* in_sizes, int n_in,
                              void* d_out, int out_size)
{
    const float* x    = (const float*)d_in[0];
    const float* W    = (const float*)d_in[1];
    const float* attS = (const float*)d_in[2];
    const float* attD = (const float*)d_in[3];
    const float* bias = (const float*)d_in[4];
    const int*   ei   = (const int*)d_in[5];

    int n = in_sizes[0] / FH;        // 50000
    int E = in_sizes[5] / 2;         // 800000
    const int* src = ei;
    const int* dst = ei + E;

    k_csrbuild<<<NTB, 256>>>(src, dst, n, E);
    k_gemm<<<(n + 127) / 128, 256>>>(x, W, attS, attD, n);
    k_agg<<<(n * 32 + 255) / 256, 256>>>(bias, (float*)d_out, n);
}

// round 9
// speedup vs baseline: 1.1315x; 1.1315x over previous
#include <cuda_runtime.h>
#include <math.h>
#include <stdint.h>

#define NN    50000
#define FH    128      // H*C
#define NH    4
#define EMAX  800000
#define NEG   0.2f
#define NBMAX 256      // >= ceil(NN/256) scan blocks

// ---------------- scratch (static device globals; no runtime alloc) --------
__device__ float  g_xp[NN * FH];         // projected features fp32 [N][128]
__device__ float  g_asrc[NN * NH];
__device__ float  g_adst[NN * NH];
__device__ int    g_deg[NN];             // real-edge counts; re-zeroed in scan
__device__ int    g_ord[EMAX];           // per-edge ordinal within its dst row
__device__ int    g_rowptr[NN + 1];
__device__ int    g_bval[NBMAX];
__device__ volatile int g_bflag[NBMAX];
__device__ int    g_csr[EMAX + NN];

// ---------------- helpers ---------------------------------------------------
__device__ __forceinline__ void f2tf32x2(float f, uint32_t& hi, uint32_t& lo) {
    asm("cvt.rna.tf32.f32 %0, %1;" : "=r"(hi) : "f"(f));
    float d = f - __uint_as_float(hi);
    asm("cvt.rna.tf32.f32 %0, %1;" : "=r"(lo) : "f"(d));
}

__device__ __forceinline__ void mma_tf32(float* c, const uint32_t* a, const uint32_t* b) {
    asm volatile(
        "mma.sync.aligned.m16n8k8.row.col.f32.tf32.tf32.f32 "
        "{%0,%1,%2,%3}, {%4,%5,%6,%7}, {%8,%9}, {%0,%1,%2,%3};"
        : "+f"(c[0]), "+f"(c[1]), "+f"(c[2]), "+f"(c[3])
        : "r"(a[0]), "r"(a[1]), "r"(a[2]), "r"(a[3]), "r"(b[0]), "r"(b[1]));
}

__device__ __forceinline__ void ffma2(unsigned long long& acc, unsigned long long v,
                                      unsigned long long w2) {
    asm("fma.rn.f32x2 %0, %1, %2, %0;" : "+l"(acc) : "l"(v), "l"(w2));
}

// ---------------- histogram: per-edge ordinal + scan-state reset ------------
__global__ void k_hist(const int* __restrict__ dst, int E) {
    int e = blockIdx.x * blockDim.x + threadIdx.x;
    if (blockIdx.x == 0 && threadIdx.x < NBMAX) g_bflag[threadIdx.x] = 0;
    if (e < E) {
        int d = __ldcs(dst + e);
        g_ord[e] = atomicAdd(&g_deg[d], 1);
    }
}

// ---------------- GEMM: xp = x @ W^T via 3xTF32 tensor cores ----------------
#define XP 20
#define WP 136
__global__ __launch_bounds__(256) void k_gemm(
    const float* __restrict__ x, const float* __restrict__ W,
    const float* __restrict__ attS, const float* __restrict__ attD, int n)
{
    __shared__ float xsh[128 * XP], xsl[128 * XP];
    __shared__ float wth[16 * WP],  wtl[16 * WP];
    __shared__ float sAttS[128], sAttD[128];
    __shared__ float sAs[128 * 4], sAd[128 * 4];

    int t = threadIdx.x;
    if (t < 128) { sAttS[t] = attS[t]; sAttD[t] = attD[t]; }

    int row0 = blockIdx.x * 128;
    int wid = t >> 5, lane = t & 31;
    int wm = wid >> 1, wn = wid & 1;
    int g = lane >> 2, q4 = lane & 3;

    float acc[2][8][4];
#pragma unroll
    for (int mt = 0; mt < 2; mt++)
#pragma unroll
        for (int nt = 0; nt < 8; nt++)
#pragma unroll
            for (int c = 0; c < 4; c++) acc[mt][nt][c] = 0.f;

    for (int kc = 0; kc < 128; kc += 16) {
#pragma unroll
        for (int j = 0; j < 2; j++) {
            int idx = t + 256 * j;
            int r = idx >> 2, q = idx & 3;
            float4 v = make_float4(0.f, 0.f, 0.f, 0.f);
            if (row0 + r < n) v = *(const float4*)(x + (size_t)(row0 + r) * 128 + kc + q * 4);
            uint32_t h0, l0, h1, l1, h2, l2, h3, l3;
            f2tf32x2(v.x, h0, l0); f2tf32x2(v.y, h1, l1);
            f2tf32x2(v.z, h2, l2); f2tf32x2(v.w, h3, l3);
            float* ph = xsh + r * XP + q * 4;
            float* pl = xsl + r * XP + q * 4;
            ph[0] = __uint_as_float(h0); ph[1] = __uint_as_float(h1);
            ph[2] = __uint_as_float(h2); ph[3] = __uint_as_float(h3);
            pl[0] = __uint_as_float(l0); pl[1] = __uint_as_float(l1);
            pl[2] = __uint_as_float(l2); pl[3] = __uint_as_float(l3);
        }
#pragma unroll
        for (int j = 0; j < 2; j++) {
            int idx = t + 256 * j;
            int oc = idx >> 2, q = idx & 3;
            float4 v = *(const float4*)(W + (size_t)oc * 128 + kc + q * 4);
            uint32_t h0, l0, h1, l1, h2, l2, h3, l3;
            f2tf32x2(v.x, h0, l0); f2tf32x2(v.y, h1, l1);
            f2tf32x2(v.z, h2, l2); f2tf32x2(v.w, h3, l3);
            wth[(q * 4 + 0) * WP + oc] = __uint_as_float(h0);
            wth[(q * 4 + 1) * WP + oc] = __uint_as_float(h1);
            wth[(q * 4 + 2) * WP + oc] = __uint_as_float(h2);
            wth[(q * 4 + 3) * WP + oc] = __uint_as_float(h3);
            wtl[(q * 4 + 0) * WP + oc] = __uint_as_float(l0);
            wtl[(q * 4 + 1) * WP + oc] = __uint_as_float(l1);
            wtl[(q * 4 + 2) * WP + oc] = __uint_as_float(l2);
            wtl[(q * 4 + 3) * WP + oc] = __uint_as_float(l3);
        }
        __syncthreads();

#pragma unroll
        for (int kk = 0; kk < 16; kk += 8) {
            uint32_t ah[2][4], al[2][4];
#pragma unroll
            for (int mt = 0; mt < 2; mt++) {
                int r = wm * 32 + mt * 16 + g;
                int b0 = r * XP + kk + q4;
                ah[mt][0] = __float_as_uint(xsh[b0]);
                ah[mt][1] = __float_as_uint(xsh[b0 + 8 * XP]);
                ah[mt][2] = __float_as_uint(xsh[b0 + 4]);
                ah[mt][3] = __float_as_uint(xsh[b0 + 8 * XP + 4]);
                al[mt][0] = __float_as_uint(xsl[b0]);
                al[mt][1] = __float_as_uint(xsl[b0 + 8 * XP]);
                al[mt][2] = __float_as_uint(xsl[b0 + 4]);
                al[mt][3] = __float_as_uint(xsl[b0 + 8 * XP + 4]);
            }
#pragma unroll
            for (int nt = 0; nt < 8; nt++) {
                int col = wn * 64 + nt * 8 + g;
                int kb = (kk + q4) * WP + col;
                uint32_t bh[2], bl[2];
                bh[0] = __float_as_uint(wth[kb]);
                bh[1] = __float_as_uint(wth[kb + 4 * WP]);
                bl[0] = __float_as_uint(wtl[kb]);
                bl[1] = __float_as_uint(wtl[kb + 4 * WP]);
#pragma unroll
                for (int mt = 0; mt < 2; mt++) {
                    mma_tf32(acc[mt][nt], ah[mt], bh);
                    mma_tf32(acc[mt][nt], ah[mt], bl);
                    mma_tf32(acc[mt][nt], al[mt], bh);
                }
            }
        }
        __syncthreads();
    }

#pragma unroll
    for (int mt = 0; mt < 2; mt++) {
#pragma unroll
        for (int half = 0; half < 2; half++) {
            int rl = wm * 32 + mt * 16 + half * 8 + g;
            int r = row0 + rl;
            float ps0 = 0.f, pd0 = 0.f, ps1 = 0.f, pd1 = 0.f;
#pragma unroll
            for (int nt = 0; nt < 8; nt++) {
                int cbase = wn * 64 + nt * 8 + q4 * 2;
                float v0 = acc[mt][nt][half * 2 + 0];
                float v1 = acc[mt][nt][half * 2 + 1];
                float as0 = sAttS[cbase], as1 = sAttS[cbase + 1];
                float ad0 = sAttD[cbase], ad1 = sAttD[cbase + 1];
                if (nt < 4) { ps0 += v0 * as0 + v1 * as1; pd0 += v0 * ad0 + v1 * ad1; }
                else        { ps1 += v0 * as0 + v1 * as1; pd1 += v0 * ad0 + v1 * ad1; }
                if (r < n)
                    *(float2*)(g_xp + (size_t)r * 128 + cbase) = make_float2(v0, v1);
            }
            ps0 += __shfl_xor_sync(0xffffffffu, ps0, 1); ps0 += __shfl_xor_sync(0xffffffffu, ps0, 2);
            ps1 += __shfl_xor_sync(0xffffffffu, ps1, 1); ps1 += __shfl_xor_sync(0xffffffffu, ps1, 2);
            pd0 += __shfl_xor_sync(0xffffffffu, pd0, 1); pd0 += __shfl_xor_sync(0xffffffffu, pd0, 2);
            pd1 += __shfl_xor_sync(0xffffffffu, pd1, 1); pd1 += __shfl_xor_sync(0xffffffffu, pd1, 2);
            if (q4 == 0) {
                sAs[rl * 4 + wn * 2 + 0] = ps0;
                sAs[rl * 4 + wn * 2 + 1] = ps1;
                sAd[rl * 4 + wn * 2 + 0] = pd0;
                sAd[rl * 4 + wn * 2 + 1] = pd1;
            }
        }
    }
    __syncthreads();
    if (t < 128 && row0 + t < n) {
        *(float4*)(g_asrc + (size_t)(row0 + t) * 4) = *(const float4*)(sAs + t * 4);
        *(float4*)(g_adst + (size_t)(row0 + t) * 4) = *(const float4*)(sAd + t * 4);
    }
}

// ---------------- scan: rowptr from deg (+1 self loop), lookback ------------
__global__ __launch_bounds__(256) void k_scan(int n, int nscan) {
    __shared__ int s[256];
    int t = threadIdx.x, b = blockIdx.x, i = b * 256 + t;
    int v = 0;
    if (i < n) { v = g_deg[i] + 1; g_deg[i] = 0; }
    s[t] = v;
    __syncthreads();
#pragma unroll
    for (int off = 1; off < 256; off <<= 1) {
        int u = (t >= off) ? s[t - off] : 0;
        __syncthreads();
        s[t] += u;
        __syncthreads();
    }
    int incl = s[t];
    int agg  = s[255];
    if (t == 255) {
        g_bval[b] = agg;
        __threadfence();
        g_bflag[b] = 1;
    }
    int part = 0;
    for (int j = t; j < b; j += 256) {
        while (g_bflag[j] == 0) { }
        part += *(volatile int*)&g_bval[j];
    }
    __syncthreads();
    s[t] = part;
    __syncthreads();
#pragma unroll
    for (int off = 128; off > 0; off >>= 1) {
        if (t < off) s[t] += s[t + off];
        __syncthreads();
    }
    int excl0 = s[0];
    if (i < n) g_rowptr[i] = excl0 + incl - v;
    if (b == nscan - 1 && t == 255) g_rowptr[n] = excl0 + agg;
}

// ---------------- scatter: atomic-free via precomputed ordinals -------------
__global__ void k_scatter(const int* __restrict__ src, const int* __restrict__ dst,
                          int E, int n) {
    int e = blockIdx.x * blockDim.x + threadIdx.x;
    int total = E + n;
    if (e >= total) return;
    if (e < E) {
        int d = __ldcs(dst + e);
        int p = g_rowptr[d] + __ldcs(g_ord + e);
        g_csr[p] = __ldcs(src + e);
    } else {
        int i = e - E;
        g_csr[g_rowptr[i + 1] - 1] = i;      // self loop in last slot
    }
}

// ---------------- aggregation: one warp per destination node ----------------
__global__ __launch_bounds__(256) void k_agg(
    const float* __restrict__ bias, float* __restrict__ out, int n)
{
    int warp = (blockIdx.x * blockDim.x + threadIdx.x) >> 5;
    int lane = threadIdx.x & 31;
    if (warp >= n) return;
    int nd = warp;
    int h = lane >> 3;

    int begin = g_rowptr[nd], end = g_rowptr[nd + 1];
    float adh = g_adst[nd * 4 + h];

    unsigned long long acc01 = 0ull, acc23 = 0ull;   // packed f32x2 accumulators
    float den = 0.f;
    const float* xpb = g_xp + lane * 4;

    int i = begin;
    for (; i + 4 <= end; i += 4) {
        int s0 = g_csr[i], s1 = g_csr[i + 1], s2 = g_csr[i + 2], s3 = g_csr[i + 3];
        float a0 = g_asrc[s0 * 4 + h] + adh;
        float a1 = g_asrc[s1 * 4 + h] + adh;
        float a2 = g_asrc[s2 * 4 + h] + adh;
        float a3 = g_asrc[s3 * 4 + h] + adh;
        ulonglong2 u0 = *(const ulonglong2*)(xpb + (size_t)s0 * 128);
        ulonglong2 u1 = *(const ulonglong2*)(xpb + (size_t)s1 * 128);
        ulonglong2 u2 = *(const ulonglong2*)(xpb + (size_t)s2 * 128);
        ulonglong2 u3 = *(const ulonglong2*)(xpb + (size_t)s3 * 128);
        a0 = fmaxf(a0, NEG * a0);
        a1 = fmaxf(a1, NEG * a1);
        a2 = fmaxf(a2, NEG * a2);
        a3 = fmaxf(a3, NEG * a3);
        float w0 = __expf(a0), w1 = __expf(a1), w2 = __expf(a2), w3 = __expf(a3);
        unsigned long long ww;
        asm("mov.b64 %0, {%1, %1};" : "=l"(ww) : "f"(w0));
        ffma2(acc01, u0.x, ww); ffma2(acc23, u0.y, ww);
        asm("mov.b64 %0, {%1, %1};" : "=l"(ww) : "f"(w1));
        ffma2(acc01, u1.x, ww); ffma2(acc23, u1.y, ww);
        asm("mov.b64 %0, {%1, %1};" : "=l"(ww) : "f"(w2));
        ffma2(acc01, u2.x, ww); ffma2(acc23, u2.y, ww);
        asm("mov.b64 %0, {%1, %1};" : "=l"(ww) : "f"(w3));
        ffma2(acc01, u3.x, ww); ffma2(acc23, u3.y, ww);
        den += (w0 + w1) + (w2 + w3);
    }
    for (; i < end; i++) {
        int s0 = g_csr[i];
        float a0 = g_asrc[s0 * 4 + h] + adh;
        ulonglong2 u0 = *(const ulonglong2*)(xpb + (size_t)s0 * 128);
        a0 = fmaxf(a0, NEG * a0);
        float w0 = __expf(a0);
        unsigned long long ww;
        asm("mov.b64 %0, {%1, %1};" : "=l"(ww) : "f"(w0));
        ffma2(acc01, u0.x, ww); ffma2(acc23, u0.y, ww);
        den += w0;
    }

    float ax, ay, az, aw;
    asm("mov.b64 {%0, %1}, %2;" : "=f"(ax), "=f"(ay) : "l"(acc01));
    asm("mov.b64 {%0, %1}, %2;" : "=f"(az), "=f"(aw) : "l"(acc23));

    float inv = 1.0f / (den + 1e-16f);
    float4 bb = ((const float4*)bias)[lane];
    float4 o;
    o.x = ax * inv + bb.x;
    o.y = ay * inv + bb.y;
    o.z = az * inv + bb.z;
    o.w = aw * inv + bb.w;
    o.x = o.x > 0.f ? o.x : expm1f(o.x);
    o.y = o.y > 0.f ? o.y : expm1f(o.y);
    o.z = o.z > 0.f ? o.z : expm1f(o.z);
    o.w = o.w > 0.f ? o.w : expm1f(o.w);
    ((float4*)out)[(size_t)nd * 32 + lane] = o;
}

// ---------------- launch: GEMM overlapped with CSR chain --------------------
extern "C" void kernel_launch(void* const* d_in, const int* in_sizes, int n_in,
                              void* d_out, int out_size)
{
    const float* x    = (const float*)d_in[0];
    const float* W    = (const float*)d_in[1];
    const float* attS = (const float*)d_in[2];
    const float* attD = (const float*)d_in[3];
    const float* bias = (const float*)d_in[4];
    const int*   ei   = (const int*)d_in[5];

    int n = in_sizes[0] / FH;        // 50000
    int E = in_sizes[5] / 2;         // 800000
    const int* src = ei;
    const int* dst = ei + E;

    int nscan = (n + 255) / 256;     // 196

    // host-side resources, created once (host objects only; no device memory)
    static cudaStream_t s_side = nullptr;
    static cudaEvent_t  ev_fork = nullptr, ev_join = nullptr;
    if (s_side == nullptr) {
        cudaStreamCreateWithFlags(&s_side, cudaStreamNonBlocking);
        cudaEventCreateWithFlags(&ev_fork, cudaEventDisableTiming);
        cudaEventCreateWithFlags(&ev_join, cudaEventDisableTiming);
    }

    // fork: GEMM on side stream, CSR chain on main stream — independent work
    cudaEventRecord(ev_fork, 0);
    cudaStreamWaitEvent(s_side, ev_fork, 0);
    k_gemm<<<(n + 127) / 128, 256, 0, s_side>>>(x, W, attS, attD, n);
    cudaEventRecord(ev_join, s_side);

    k_hist<<<(E + 255) / 256, 256>>>(dst, E);
    k_scan<<<nscan, 256>>>(n, nscan);
    k_scatter<<<(E + n + 255) / 256, 256>>>(src, dst, E, n);

    // join: aggregation needs both GEMM outputs and CSR
    cudaStreamWaitEvent(0, ev_join, 0);
    k_agg<<<(n * 32 + 255) / 256, 256>>>(bias, (float*)d_out, n);
}